// round 11
// baseline (speedup 1.0000x reference)
#include <cuda_runtime.h>
#include <cuda_fp16.h>
#include <math.h>
#include <stdint.h>

// HashEmbedder: 16-level 2D multires hash grid, 2 feats/level, T=2^19.
// Phase 1: build fp16 cell-packed corner table (16B per cell).
// Phase 2: warp-uniform level groups: each warp = 32 consecutive points x
// one 4-level group. Level params are read via warp-uniform LDC from the
// kernel-param constant bank (constant port) -> ZERO l1tex traffic for
// params (R5 spent ~6M LDS wavefronts on them). Gathers: 4x LDG.128, MLP=4.

#define NLEV 16
#define TLOG2 19
#define TSIZE (1u << TLOG2)
#define HMASK ((1u << TLOG2) - 1u)
#define PRIME1 2654435761u

// Sum of res^2 over the 16 levels = 706,816 cells; margin for safety.
#define MAX_CELLS 710000
__device__ uint4 g_packed[MAX_CELLS];   // 16B per cell: h00,h10,h01,h11

struct Params {
    float resF[NLEV];
    int   resI[NLEV];
    int   off[NLEV];
    int   total;
};

// ---------------------------------------------------------------------------
// Phase 1: build packed table. One thread per cell.
// ---------------------------------------------------------------------------
__global__ __launch_bounds__(256) void build_packed_kernel(
    const float* __restrict__ emb, Params pm, int total_cells)
{
    int i = blockIdx.x * blockDim.x + threadIdx.x;
    if (i >= total_cells) return;

    int l = 0;
#pragma unroll
    for (int k = 1; k < NLEV; ++k) l += (i >= pm.off[k]);

    int c   = i - pm.off[l];
    int res = pm.resI[l];
    int cy  = c / res;
    int cx  = c - cy * res;

    uint32_t ux0 = (uint32_t)cx;
    uint32_t ux1 = (uint32_t)(cx + 1);
    uint32_t yp0 = (uint32_t)cy * PRIME1;
    uint32_t yp1 = (uint32_t)(cy + 1) * PRIME1;

    uint32_t a00 = (ux0 ^ yp0) & HMASK;
    uint32_t a10 = (ux1 ^ yp0) & HMASK;
    uint32_t a01 = (ux0 ^ yp1) & HMASK;
    uint32_t a11 = (ux1 ^ yp1) & HMASK;

    const float2* __restrict__ tab =
        ((const float2*)emb) + ((size_t)l << TLOG2);

    float2 f00 = __ldg(tab + a00);
    float2 f10 = __ldg(tab + a10);
    float2 f01 = __ldg(tab + a01);
    float2 f11 = __ldg(tab + a11);

    half2 h00 = __float22half2_rn(f00);
    half2 h10 = __float22half2_rn(f10);
    half2 h01 = __float22half2_rn(f01);
    half2 h11 = __float22half2_rn(f11);

    uint4 r;
    r.x = *(const uint32_t*)&h00;
    r.y = *(const uint32_t*)&h10;
    r.z = *(const uint32_t*)&h01;
    r.w = *(const uint32_t*)&h11;
    g_packed[i] = r;
}

// ---------------------------------------------------------------------------
// Phase 2: warp = 32 consecutive points x one warp-uniform 4-level group.
// ---------------------------------------------------------------------------
__global__ __launch_bounds__(256) void hash_embed_kernel(
    const float* __restrict__ x,
    float* __restrict__ out,
    int n_points,
    Params pm)
{
    int gwarp = (blockIdx.x * blockDim.x + threadIdx.x) >> 5;
    int lane  = threadIdx.x & 31;

    int pb = gwarp >> 2;            // point-block (32 points)
    int lb = (gwarp & 3) << 2;      // warp-uniform base level: 0,4,8,12

    int p = pb * 32 + lane;
    if (p >= n_points) return;

    // lane-consecutive -> 2 lines per warp
    float2 xy = __ldg(((const float2*)x) + p);

    int   idx[4];
    float wx[4], wy[4];

#pragma unroll
    for (int j = 0; j < 4; ++j) {
        int   l   = lb + j;         // warp-uniform index -> LDC, constant port
        float res = pm.resF[l];
        int   ri  = pm.resI[l];
        int   off = pm.off[l];

        float px = xy.x * res;
        float py = xy.y * res;
        float fx = floorf(px);
        float fy = floorf(py);
        wx[j] = px - fx;
        wy[j] = py - fy;

        int ix = min(max((int)fx, 0), ri - 1);
        int iy = min(max((int)fy, 0), ri - 1);
        idx[j] = off + iy * ri + ix;
    }

    // 4 independent gathers, issued back-to-back (MLP=4)
    uint4 r0 = __ldg(&g_packed[idx[0]]);
    uint4 r1 = __ldg(&g_packed[idx[1]]);
    uint4 r2 = __ldg(&g_packed[idx[2]]);
    uint4 r3 = __ldg(&g_packed[idx[3]]);

    float o[8];
    uint4 rr[4] = {r0, r1, r2, r3};
#pragma unroll
    for (int j = 0; j < 4; ++j) {
        float2 f00 = __half22float2(*(const half2*)&rr[j].x);
        float2 f10 = __half22float2(*(const half2*)&rr[j].y);
        float2 f01 = __half22float2(*(const half2*)&rr[j].z);
        float2 f11 = __half22float2(*(const half2*)&rr[j].w);

        float u = 1.0f - wx[j];
        float v = 1.0f - wy[j];

        o[2 * j]     = (f00.x * u + f10.x * wx[j]) * v + (f01.x * u + f11.x * wx[j]) * wy[j];
        o[2 * j + 1] = (f00.y * u + f10.y * wx[j]) * v + (f01.y * u + f11.y * wx[j]) * wy[j];
    }

    // thread covers floats [lb*2, lb*2+8) of point p's row -> 32B.
    float4* dst = (float4*)(out + (size_t)p * (NLEV * 2) + lb * 2);
    dst[0] = make_float4(o[0], o[1], o[2], o[3]);
    dst[1] = make_float4(o[4], o[5], o[6], o[7]);
}

extern "C" void kernel_launch(void* const* d_in, const int* in_sizes, int n_in,
                              void* d_out, int out_size)
{
    const float* x   = (const float*)d_in[0];
    const float* emb = (const float*)d_in[1];
    float* out       = (float*)d_out;

    int n_points = in_sizes[0] / 2;

    Params pm;
    double b = exp((log(512.0) - log(16.0)) / 15.0);
    int acc = 0;
    for (int l = 0; l < NLEV; ++l) {
        double r = floor(16.0 * pow(b, (double)l));
        pm.resF[l] = (float)r;
        pm.resI[l] = (int)r;
        pm.off[l]  = acc;
        acc += pm.resI[l] * pm.resI[l];
    }
    pm.total = acc;

    // Phase 1: build packed corner table (fp16, 16B per cell)
    {
        int threads = 256;
        int blocks = (acc + threads - 1) / threads;
        build_packed_kernel<<<blocks, threads>>>(emb, pm, acc);
    }

    // Phase 2: gather + lerp; warp = 32 points x 4 levels
    {
        int pblocks = (n_points + 31) / 32;          // 32-point groups
        long long warps = (long long)pblocks * 4;    // x 4 level groups
        long long total = warps * 32;
        int threads = 256;
        int blocks = (int)((total + threads - 1) / threads);
        hash_embed_kernel<<<blocks, threads>>>(x, out, n_points, pm);
    }
}

// round 12
// speedup vs baseline: 1.2420x; 1.2420x over previous
#include <cuda_runtime.h>
#include <cuda_fp16.h>
#include <math.h>
#include <stdint.h>

// HashEmbedder: 16-level 2D multires hash grid, 2 feats/level, T=2^19.
// Phase 1: build fp16 cell-packed corner table (16B per cell).
// Phase 2 (R5 shape): 4 thr/point, 4 levels/thread, MLP=4.
//   levels 0-7  (264KB ~ L1): __ldg  -> L1-resident after compulsory fills
//   levels 8-15 (10.8MB)    : __ldcg -> L2 only, no L1 fills/evictions
// Level params packed as one float4 per level in SMEM (1 LDS.128 / level).

#define NLEV 16
#define TLOG2 19
#define TSIZE (1u << TLOG2)
#define HMASK ((1u << TLOG2) - 1u)
#define PRIME1 2654435761u

// Sum of res^2 over the 16 levels = 706,816 cells; margin for safety.
#define MAX_CELLS 710000
__device__ uint4 g_packed[MAX_CELLS];   // 16B per cell: h00,h10,h01,h11

struct Params {
    float resF[NLEV];
    int   resI[NLEV];
    int   off[NLEV];
    int   total;
};

// ---------------------------------------------------------------------------
// Phase 1: build packed table. One thread per cell.
// ---------------------------------------------------------------------------
__global__ __launch_bounds__(256) void build_packed_kernel(
    const float* __restrict__ emb, Params pm, int total_cells)
{
    int i = blockIdx.x * blockDim.x + threadIdx.x;
    if (i >= total_cells) return;

    int l = 0;
#pragma unroll
    for (int k = 1; k < NLEV; ++k) l += (i >= pm.off[k]);

    int c   = i - pm.off[l];
    int res = pm.resI[l];
    int cy  = c / res;
    int cx  = c - cy * res;

    uint32_t ux0 = (uint32_t)cx;
    uint32_t ux1 = (uint32_t)(cx + 1);
    uint32_t yp0 = (uint32_t)cy * PRIME1;
    uint32_t yp1 = (uint32_t)(cy + 1) * PRIME1;

    uint32_t a00 = (ux0 ^ yp0) & HMASK;
    uint32_t a10 = (ux1 ^ yp0) & HMASK;
    uint32_t a01 = (ux0 ^ yp1) & HMASK;
    uint32_t a11 = (ux1 ^ yp1) & HMASK;

    const float2* __restrict__ tab =
        ((const float2*)emb) + ((size_t)l << TLOG2);

    float2 f00 = __ldg(tab + a00);
    float2 f10 = __ldg(tab + a10);
    float2 f01 = __ldg(tab + a01);
    float2 f11 = __ldg(tab + a11);

    half2 h00 = __float22half2_rn(f00);
    half2 h10 = __float22half2_rn(f10);
    half2 h01 = __float22half2_rn(f01);
    half2 h11 = __float22half2_rn(f11);

    uint4 r;
    r.x = *(const uint32_t*)&h00;
    r.y = *(const uint32_t*)&h10;
    r.z = *(const uint32_t*)&h01;
    r.w = *(const uint32_t*)&h11;
    g_packed[i] = r;
}

// ---------------------------------------------------------------------------
// Phase 2: one thread per (point, 4-level group). MLP=4 gathers.
// ---------------------------------------------------------------------------
__global__ __launch_bounds__(256) void hash_embed_kernel(
    const float* __restrict__ x,
    float* __restrict__ out,
    int n_points,
    Params pm)
{
    // One float4 per level: {resF, resI (bits), off (bits), 0}
    __shared__ float4 s_lv[NLEV];
    if (threadIdx.x < NLEV) {
        s_lv[threadIdx.x] = make_float4(
            pm.resF[threadIdx.x],
            __int_as_float(pm.resI[threadIdx.x]),
            __int_as_float(pm.off[threadIdx.x]),
            0.0f);
    }
    __syncthreads();

    int gid = blockIdx.x * blockDim.x + threadIdx.x;
    int p = gid >> 2;              // point index (4 threads per point)
    if (p >= n_points) return;
    int lb = (gid & 3) << 2;       // base level: 0,4,8,12

    // 4 consecutive threads read the same point -> broadcast load
    float2 xy = __ldg(((const float2*)x) + p);

    int   idx[4];
    float wx[4], wy[4];

#pragma unroll
    for (int j = 0; j < 4; ++j) {
        float4 lv  = s_lv[lb + j];       // single LDS.128
        float  res = lv.x;
        int    ri  = __float_as_int(lv.y);
        int    off = __float_as_int(lv.z);

        float px = xy.x * res;
        float py = xy.y * res;
        float fx = floorf(px);
        float fy = floorf(py);
        wx[j] = px - fx;
        wy[j] = py - fy;

        int ix = min(max((int)fx, 0), ri - 1);
        int iy = min(max((int)fy, 0), ri - 1);
        idx[j] = off + iy * ri + ix;
    }

    uint4 rr[4];
    if (lb < 8) {
        // coarse levels 0-7 (264KB total): default L1-caching path
#pragma unroll
        for (int j = 0; j < 4; ++j) rr[j] = __ldg(&g_packed[idx[j]]);
    } else {
        // fine levels 8-15 (10.8MB): L2-only, avoid L1 fills/evictions
#pragma unroll
        for (int j = 0; j < 4; ++j) {
            uint4 v;
            asm("ld.global.cg.v4.u32 {%0,%1,%2,%3}, [%4];"
                : "=r"(v.x), "=r"(v.y), "=r"(v.z), "=r"(v.w)
                : "l"(&g_packed[idx[j]]));
            rr[j] = v;
        }
    }

    float o[8];
#pragma unroll
    for (int j = 0; j < 4; ++j) {
        float2 f00 = __half22float2(*(const half2*)&rr[j].x);
        float2 f10 = __half22float2(*(const half2*)&rr[j].y);
        float2 f01 = __half22float2(*(const half2*)&rr[j].z);
        float2 f11 = __half22float2(*(const half2*)&rr[j].w);

        float u = 1.0f - wx[j];
        float v = 1.0f - wy[j];

        o[2 * j]     = (f00.x * u + f10.x * wx[j]) * v + (f01.x * u + f11.x * wx[j]) * wy[j];
        o[2 * j + 1] = (f00.y * u + f10.y * wx[j]) * v + (f01.y * u + f11.y * wx[j]) * wy[j];
    }

    // out row = p*32 floats; this thread covers floats [lb*2, lb*2+8) = 32B.
    // 4 threads per point -> a full 128B line, perfectly coalesced.
    float4* dst = (float4*)(out + (size_t)p * (NLEV * 2) + lb * 2);
    dst[0] = make_float4(o[0], o[1], o[2], o[3]);
    dst[1] = make_float4(o[4], o[5], o[6], o[7]);
}

extern "C" void kernel_launch(void* const* d_in, const int* in_sizes, int n_in,
                              void* d_out, int out_size)
{
    const float* x   = (const float*)d_in[0];
    const float* emb = (const float*)d_in[1];
    float* out       = (float*)d_out;

    int n_points = in_sizes[0] / 2;

    Params pm;
    double b = exp((log(512.0) - log(16.0)) / 15.0);
    int acc = 0;
    for (int l = 0; l < NLEV; ++l) {
        double r = floor(16.0 * pow(b, (double)l));
        pm.resF[l] = (float)r;
        pm.resI[l] = (int)r;
        pm.off[l]  = acc;
        acc += pm.resI[l] * pm.resI[l];
    }
    pm.total = acc;

    // Phase 1: build packed corner table (fp16, 16B per cell)
    {
        int threads = 256;
        int blocks = (acc + threads - 1) / threads;
        build_packed_kernel<<<blocks, threads>>>(emb, pm, acc);
    }

    // Phase 2: gather + lerp, 4 threads per point
    {
        long long total = (long long)n_points * 4;
        int threads = 256;
        int blocks = (int)((total + threads - 1) / threads);
        hash_embed_kernel<<<blocks, threads>>>(x, out, n_points, pm);
    }
}